// round 1
// baseline (speedup 1.0000x reference)
#include <cuda_runtime.h>
#include <cstdint>

#define TOKENS 64
#define IN_F   4096
#define OUT_F  11008
#define RANK   16

// scratch for t = x @ A^T  (64 x 16)
__device__ float g_t[TOKENS * RANK];

typedef unsigned long long u64;

__device__ __forceinline__ u64 pack2(float v) {
    u64 r;
    unsigned int b = __float_as_uint(v);
    asm("mov.b64 %0, {%1, %2};" : "=l"(r) : "r"(b), "r"(b));
    return r;
}
__device__ __forceinline__ u64 fma2(u64 a, u64 b, u64 c) {
    u64 d;
    asm("fma.rn.f32x2 %0, %1, %2, %3;" : "=l"(d) : "l"(a), "l"(b), "l"(c));
    return d;
}
__device__ __forceinline__ float2 unpack2(u64 v) {
    unsigned int lo, hi;
    asm("mov.b64 {%0, %1}, %2;" : "=r"(lo), "=r"(hi) : "l"(v));
    return make_float2(__uint_as_float(lo), __uint_as_float(hi));
}

// ---------------------------------------------------------------------------
// Kernel 1: t[m][r] = sum_k x[m][k] * A[r][k]    (64 blocks, 128 threads)
// Deterministic shared-memory tree reduction (no fp atomics).
// ---------------------------------------------------------------------------
__global__ void __launch_bounds__(128) lora_t_kernel(
    const float* __restrict__ x, const float* __restrict__ A)
{
    __shared__ float sp[128][RANK];
    const int m   = blockIdx.x;
    const int tid = threadIdx.x;

    float racc[RANK];
#pragma unroll
    for (int r = 0; r < RANK; r++) racc[r] = 0.0f;

    for (int k = tid; k < IN_F; k += 128) {
        float xv = x[m * IN_F + k];
#pragma unroll
        for (int r = 0; r < RANK; r++)
            racc[r] += xv * A[r * IN_F + k];
    }
#pragma unroll
    for (int r = 0; r < RANK; r++) sp[tid][r] = racc[r];
    __syncthreads();

    if (tid < RANK) {
        float s = 0.0f;
        for (int i = 0; i < 128; i++) s += sp[i][tid];
        g_t[m * RANK + tid] = s;   // ALPHA/RANK == 1.0, no extra factor
    }
}

// ---------------------------------------------------------------------------
// Kernel 2: main GEMM  out[m][n] = scale[n]*dot(x[m],W[n]) + dot16(t[m],B[n]) + bias[n]
// BM=64 (all tokens), BN=64 (grid 172), BK=32, 256 threads, 4x4 microtile,
// f32x2 packed FMA, register prefetch for latency hiding.
// ---------------------------------------------------------------------------
#define BM 64
#define BN 64
#define BK 32

__global__ void __launch_bounds__(256) lora_gemm_kernel(
    const float* __restrict__ x,    const float* __restrict__ W,
    const float* __restrict__ scale,const float* __restrict__ Bl,
    const float* __restrict__ bias, float* __restrict__ out)
{
    __shared__ float As[BK][BM];          // x tile, transposed: As[k][m]
    __shared__ float Bs[BK][BN];          // W tile, transposed: Bs[k][n]
    __shared__ float sT[TOKENS][RANK];    // t = x@A^T
    __shared__ float sB[BN][RANK + 1];    // lora_B rows for this tile

    const int tid = threadIdx.x;
    const int n0  = blockIdx.x * BN;
    const int tx  = tid & 15;   // n direction, 16
    const int ty  = tid >> 4;   // m direction, 16

    // epilogue operands into smem (done once, overlaps with first loads)
    for (int i = tid; i < TOKENS * RANK; i += 256)
        sT[i >> 4][i & 15] = g_t[i];
    for (int i = tid; i < BN * RANK; i += 256)
        sB[i >> 4][i & 15] = Bl[(n0 + (i >> 4)) * RANK + (i & 15)];

    // tile loader mapping: 2048 floats per matrix per iter = 2 float4 / thread
    const int r0 = tid >> 3;            // 0..31
    const int c0 = (tid & 7) << 2;      // 0,4,...,28
    const int r1 = r0 + 32;

    const float* xp0 = x + r0 * IN_F + c0;
    const float* xp1 = x + r1 * IN_F + c0;
    const float* wp0 = W + (n0 + r0) * IN_F + c0;
    const float* wp1 = W + (n0 + r1) * IN_F + c0;

    // prefetch first tile into registers
    float4 xa0 = *(const float4*)(xp0);
    float4 xa1 = *(const float4*)(xp1);
    float4 wb0 = *(const float4*)(wp0);
    float4 wb1 = *(const float4*)(wp1);

    u64 acc[4][2];
#pragma unroll
    for (int m = 0; m < 4; m++) { acc[m][0] = 0ULL; acc[m][1] = 0ULL; }

    for (int k0 = 0; k0 < IN_F; k0 += BK) {
        // commit prefetched tile to smem (transposed)
        As[c0 + 0][r0] = xa0.x; As[c0 + 1][r0] = xa0.y;
        As[c0 + 2][r0] = xa0.z; As[c0 + 3][r0] = xa0.w;
        As[c0 + 0][r1] = xa1.x; As[c0 + 1][r1] = xa1.y;
        As[c0 + 2][r1] = xa1.z; As[c0 + 3][r1] = xa1.w;
        Bs[c0 + 0][r0] = wb0.x; Bs[c0 + 1][r0] = wb0.y;
        Bs[c0 + 2][r0] = wb0.z; Bs[c0 + 3][r0] = wb0.w;
        Bs[c0 + 0][r1] = wb1.x; Bs[c0 + 1][r1] = wb1.y;
        Bs[c0 + 2][r1] = wb1.z; Bs[c0 + 3][r1] = wb1.w;
        __syncthreads();

        // issue next-tile loads early; latency hidden by the compute below
        const int kn = k0 + BK;
        if (kn < IN_F) {
            xa0 = *(const float4*)(xp0 + kn);
            xa1 = *(const float4*)(xp1 + kn);
            wb0 = *(const float4*)(wp0 + kn);
            wb1 = *(const float4*)(wp1 + kn);
        }

#pragma unroll
        for (int kk = 0; kk < BK; kk++) {
            float4 av = *(const float4*)&As[kk][ty << 2];
            u64 b01 = *(const u64*)&Bs[kk][(tx << 2)];
            u64 b23 = *(const u64*)&Bs[kk][(tx << 2) + 2];
            u64 a;
            a = pack2(av.x);
            acc[0][0] = fma2(a, b01, acc[0][0]);
            acc[0][1] = fma2(a, b23, acc[0][1]);
            a = pack2(av.y);
            acc[1][0] = fma2(a, b01, acc[1][0]);
            acc[1][1] = fma2(a, b23, acc[1][1]);
            a = pack2(av.z);
            acc[2][0] = fma2(a, b01, acc[2][0]);
            acc[2][1] = fma2(a, b23, acc[2][1]);
            a = pack2(av.w);
            acc[3][0] = fma2(a, b01, acc[3][0]);
            acc[3][1] = fma2(a, b23, acc[3][1]);
        }
        __syncthreads();
    }

    // epilogue: scale, LoRA delta, bias
#pragma unroll
    for (int m = 0; m < 4; m++) {
        const int row = (ty << 2) + m;
        const float* tr = sT[row];
#pragma unroll
        for (int p = 0; p < 2; p++) {
            float2 v = unpack2(acc[m][p]);
            const int nloc = (tx << 2) + (p << 1);
            float res[2] = {v.x, v.y};
#pragma unroll
            for (int q = 0; q < 2; q++) {
                const int nn = nloc + q;
                const int gn = n0 + nn;
                float l = 0.0f;
#pragma unroll
                for (int r = 0; r < RANK; r++)
                    l += tr[r] * sB[nn][r];
                out[row * OUT_F + gn] = res[q] * scale[gn] + l + bias[gn];
            }
        }
    }
}

// ---------------------------------------------------------------------------
extern "C" void kernel_launch(void* const* d_in, const int* in_sizes, int n_in,
                              void* d_out, int out_size)
{
    const float* x     = (const float*)d_in[0];  // [64, 4096]
    const float* W     = (const float*)d_in[1];  // [11008, 4096]
    const float* scale = (const float*)d_in[2];  // [11008]
    const float* A     = (const float*)d_in[3];  // [16, 4096]
    const float* B     = (const float*)d_in[4];  // [11008, 16]
    const float* bias  = (const float*)d_in[5];  // [11008]
    float* out = (float*)d_out;                  // [64, 11008]

    lora_t_kernel<<<TOKENS, 128>>>(x, A);
    lora_gemm_kernel<<<OUT_F / BN, 256>>>(x, W, scale, B, bias, out);
}

// round 3
// speedup vs baseline: 1.9468x; 1.9468x over previous
#include <cuda_runtime.h>
#include <cstdint>

#define TOKENS 64
#define IN_F   4096
#define OUT_F  11008
#define RANK   16
#define BN     128
#define BK     32
#define NITER  (IN_F / BK)   // 128

// scratch: t = x@A^T, and fragment-packed tf32 hi/lo of x
__device__ float g_t[TOKENS * RANK];
__device__ float g_xfrag[NITER * 2 * 4 * 4 * 32 * 4];   // [i][pass][mt][ks][lane][4] = 2MB

// ---------------------------------------------------------------------------
__device__ __forceinline__ uint32_t smem_u32(const void* p) {
    uint32_t a;
    asm("{ .reg .u64 t; cvta.to.shared.u64 t, %1; cvt.u32.u64 %0, t; }" : "=r"(a) : "l"(p));
    return a;
}
__device__ __forceinline__ void cp16(void* dst_smem, const void* src) {
    asm volatile("cp.async.cg.shared.global [%0], [%1], 16;"
                 :: "r"(smem_u32(dst_smem)), "l"(src));
}
__device__ __forceinline__ void mma_tf32(float* d, const uint32_t* a, const uint32_t* b) {
    asm volatile("mma.sync.aligned.m16n8k8.row.col.f32.tf32.tf32.f32 "
        "{%0,%1,%2,%3}, {%4,%5,%6,%7}, {%8,%9}, {%0,%1,%2,%3};"
        : "+f"(d[0]), "+f"(d[1]), "+f"(d[2]), "+f"(d[3])
        : "r"(a[0]), "r"(a[1]), "r"(a[2]), "r"(a[3]), "r"(b[0]), "r"(b[1]));
}
__device__ __forceinline__ float tf32_rn(float v) {
    uint32_t h;
    asm("cvt.rna.tf32.f32 %0, %1;" : "=r"(h) : "f"(v));
    return __uint_as_float(h);
}

// ---------------------------------------------------------------------------
// Kernel 1: t[m][r] = sum_k x[m][k]*A[r][k]
// ---------------------------------------------------------------------------
__global__ void __launch_bounds__(256) lora_t_kernel(
    const float* __restrict__ x, const float* __restrict__ A)
{
    const int m = blockIdx.x, tid = threadIdx.x;
    const int wid = tid >> 5, lane = tid & 31;
    const float4* x4 = (const float4*)(x + (size_t)m * IN_F);
    const float4* A4 = (const float4*)A;

    float racc[RANK];
#pragma unroll
    for (int r = 0; r < RANK; r++) racc[r] = 0.0f;
#pragma unroll
    for (int it = 0; it < 4; it++) {
        const int k4 = tid + it * 256;
        const float4 xv = x4[k4];
#pragma unroll
        for (int r = 0; r < RANK; r++) {
            const float4 av = A4[r * 1024 + k4];
            racc[r] += xv.x * av.x + xv.y * av.y + xv.z * av.z + xv.w * av.w;
        }
    }
#pragma unroll
    for (int r = 0; r < RANK; r++)
#pragma unroll
        for (int o = 16; o; o >>= 1)
            racc[r] += __shfl_xor_sync(0xFFFFFFFFu, racc[r], o);

    __shared__ float sp[8][RANK];
    if (lane == 0)
#pragma unroll
        for (int r = 0; r < RANK; r++) sp[wid][r] = racc[r];
    __syncthreads();
    if (tid < RANK) {
        float s = 0.0f;
#pragma unroll
        for (int w = 0; w < 8; w++) s += sp[w][tid];
        g_t[m * RANK + tid] = s;
    }
}

// ---------------------------------------------------------------------------
// Kernel 2: pack x into m16n8k8 tf32 A-fragments (hi = RN-tf32, lo = residual)
// ---------------------------------------------------------------------------
__global__ void __launch_bounds__(256) xfrag_kernel(const float* __restrict__ x)
{
    const int gid  = blockIdx.x * 256 + threadIdx.x;   // 65536 total
    const int lane = gid & 31;
    const int ks   = (gid >> 5) & 3;
    const int mt   = (gid >> 7) & 3;
    const int i    = gid >> 9;
    const int m    = mt * 16 + (lane >> 2);
    const int k    = i * BK + ks * 8 + (lane & 3);

    const float v00 = x[m * IN_F + k];
    const float v01 = x[m * IN_F + k + 4];
    const float v10 = x[(m + 8) * IN_F + k];
    const float v11 = x[(m + 8) * IN_F + k + 4];
    const float h00 = tf32_rn(v00), h01 = tf32_rn(v01);
    const float h10 = tf32_rn(v10), h11 = tf32_rn(v11);

    // a-reg order: a0=(g,j) a1=(g+8,j) a2=(g,j+4) a3=(g+8,j+4)
    const int slot = mt * 4 + ks;
    float4* hi = (float4*)(g_xfrag + ((size_t)(i * 2 + 0) * 16 + slot) * 128 + lane * 4);
    float4* lo = (float4*)(g_xfrag + ((size_t)(i * 2 + 1) * 16 + slot) * 128 + lane * 4);
    *hi = make_float4(h00, h10, h01, h11);
    *lo = make_float4(v00 - h00, v10 - h10, v01 - h01, v11 - h11);
}

// ---------------------------------------------------------------------------
// Kernel 3: tf32 GEMM, W fed raw (HW truncation, bias-corrected via scale).
// CTA: 64 tok x 128 ch. 8 warps (2x4), warp tile 32x32. cp.async double buffer.
// ---------------------------------------------------------------------------
#define XS_SZ    16384
#define WS_SZ    18432                 // 128 rows * 36 floats * 4B
#define STAGE_SZ (XS_SZ + WS_SZ)       // 34816
#define SMEM_SZ  (2 * STAGE_SZ)        // 69632

__global__ void __launch_bounds__(256, 1) qgemm_tf32(
    const float* __restrict__ W,     const float* __restrict__ scale,
    const float* __restrict__ Bl,    const float* __restrict__ bias,
    float* __restrict__ out)
{
    extern __shared__ char smem[];
    const int tid  = threadIdx.x;
    const int n0   = blockIdx.x * BN;
    const int warp = tid >> 5, lane = tid & 31;
    const int wm = warp >> 2, wn = warp & 3;   // 2 x 4 warp grid
    const int g  = lane >> 2, j = lane & 3;

    float acc[2][4][4];
#pragma unroll
    for (int a = 0; a < 2; a++)
#pragma unroll
        for (int b = 0; b < 4; b++)
#pragma unroll
            for (int c = 0; c < 4; c++) acc[a][b][c] = 0.0f;

    // stage loader
    const int wr = tid >> 3, wq = tid & 7;     // W: row, 16B-quad
    const float* wsrc0 = W + (size_t)(n0 + wr) * IN_F + wq * 4;

#define ISSUE_STAGE(s) do {                                                     \
    if ((s) < NITER) {                                                          \
        char* buf = smem + ((s) & 1) * STAGE_SZ;                                \
        const float* xsrc = g_xfrag + (size_t)(s) * 4096;                       \
        _Pragma("unroll")                                                       \
        for (int c = 0; c < 4; c++)                                             \
            cp16(buf + (tid + c * 256) * 16, xsrc + (tid + c * 256) * 4);       \
        _Pragma("unroll")                                                       \
        for (int sw = 0; sw < 4; sw++)                                          \
            cp16(buf + XS_SZ + (wr + sw * 32) * 144 + wq * 16,                  \
                 wsrc0 + (size_t)sw * 32 * IN_F + (s) * BK);                    \
    }                                                                           \
    asm volatile("cp.async.commit_group;" ::: "memory");                        \
} while (0)

    ISSUE_STAGE(0);
    ISSUE_STAGE(1);

#pragma unroll 1
    for (int i = 0; i < NITER; i++) {
        asm volatile("cp.async.wait_group 1;" ::: "memory");
        __syncthreads();
        const char* buf = smem + (i & 1) * STAGE_SZ;
        const uint32_t* xs = (const uint32_t*)buf;
        const uint32_t* ws = (const uint32_t*)(buf + XS_SZ);

#pragma unroll
        for (int ks = 0; ks < 4; ks++) {
            uint32_t a[2][2][4];
#pragma unroll
            for (int p = 0; p < 2; p++)
#pragma unroll
                for (int mt2 = 0; mt2 < 2; mt2++) {
                    const int mt = wm * 2 + mt2;
                    const uint4 v = *(const uint4*)(xs + ((p * 16) + mt * 4 + ks) * 128 + lane * 4);
                    a[p][mt2][0] = v.x; a[p][mt2][1] = v.y;
                    a[p][mt2][2] = v.z; a[p][mt2][3] = v.w;
                }
            uint32_t b[4][2];
#pragma unroll
            for (int nt = 0; nt < 4; nt++) {
                const int n = wn * 32 + nt * 8 + g;
                b[nt][0] = ws[n * 36 + ks * 8 + j];
                b[nt][1] = ws[n * 36 + ks * 8 + j + 4];
            }
#pragma unroll
            for (int p = 0; p < 2; p++)
#pragma unroll
                for (int mt2 = 0; mt2 < 2; mt2++)
#pragma unroll
                    for (int nt = 0; nt < 4; nt++)
                        mma_tf32(acc[mt2][nt], a[p][mt2], b[nt]);
        }
        __syncthreads();
        ISSUE_STAGE(i + 2);
    }

    // epilogue: tf32-truncation bias correction folded into scale
    const float corr = 1.00048828125f;   // 1 + 2^-11
#pragma unroll
    for (int mt2 = 0; mt2 < 2; mt2++) {
        const int tokA = wm * 32 + mt2 * 16 + g;
        const int tokB = tokA + 8;
        float4 tA0 = *(const float4*)(g_t + tokA * RANK);
        float4 tA1 = *(const float4*)(g_t + tokA * RANK + 4);
        float4 tA2 = *(const float4*)(g_t + tokA * RANK + 8);
        float4 tA3 = *(const float4*)(g_t + tokA * RANK + 12);
        float4 tB0 = *(const float4*)(g_t + tokB * RANK);
        float4 tB1 = *(const float4*)(g_t + tokB * RANK + 4);
        float4 tB2 = *(const float4*)(g_t + tokB * RANK + 8);
        float4 tB3 = *(const float4*)(g_t + tokB * RANK + 12);
#pragma unroll
        for (int nt = 0; nt < 4; nt++) {
            const int ch = n0 + wn * 32 + nt * 8 + 2 * j;
            const float2 sc = *(const float2*)(scale + ch);
            const float2 bi = *(const float2*)(bias + ch);
            const float* bl0 = Bl + (size_t)ch * RANK;
            const float* bl1 = bl0 + RANK;
            float l0 = 0.f, l0b = 0.f, l1 = 0.f, l1b = 0.f;
#pragma unroll
            for (int q = 0; q < 4; q++) {
                const float4 b0 = ((const float4*)bl0)[q];
                const float4 b1 = ((const float4*)bl1)[q];
                const float4 ta = (q == 0) ? tA0 : (q == 1) ? tA1 : (q == 2) ? tA2 : tA3;
                const float4 tb = (q == 0) ? tB0 : (q == 1) ? tB1 : (q == 2) ? tB2 : tB3;
                l0  += ta.x * b0.x + ta.y * b0.y + ta.z * b0.z + ta.w * b0.w;
                l1  += ta.x * b1.x + ta.y * b1.y + ta.z * b1.z + ta.w * b1.w;
                l0b += tb.x * b0.x + tb.y * b0.y + tb.z * b0.z + tb.w * b0.w;
                l1b += tb.x * b1.x + tb.y * b1.y + tb.z * b1.z + tb.w * b1.w;
            }
            const float s0 = sc.x * corr, s1 = sc.y * corr;
            float2 oA = make_float2(acc[mt2][nt][0] * s0 + l0  + bi.x,
                                    acc[mt2][nt][1] * s1 + l1  + bi.y);
            float2 oB = make_float2(acc[mt2][nt][2] * s0 + l0b + bi.x,
                                    acc[mt2][nt][3] * s1 + l1b + bi.y);
            *(float2*)(out + (size_t)tokA * OUT_F + ch) = oA;
            *(float2*)(out + (size_t)tokB * OUT_F + ch) = oB;
        }
    }
}

// ---------------------------------------------------------------------------
extern "C" void kernel_launch(void* const* d_in, const int* in_sizes, int n_in,
                              void* d_out, int out_size)
{
    const float* x     = (const float*)d_in[0];
    const float* W     = (const float*)d_in[1];
    const float* scale = (const float*)d_in[2];
    const float* A     = (const float*)d_in[3];
    const float* B     = (const float*)d_in[4];
    const float* bias  = (const float*)d_in[5];
    float* out = (float*)d_out;

    cudaFuncSetAttribute(qgemm_tf32, cudaFuncAttributeMaxDynamicSharedMemorySize, SMEM_SZ);
    lora_t_kernel<<<TOKENS, 256>>>(x, A);
    xfrag_kernel<<<256, 256>>>(x);
    qgemm_tf32<<<OUT_F / BN, 256, SMEM_SZ>>>(W, scale, B, bias, out);
}

// round 4
// speedup vs baseline: 4.0772x; 2.0943x over previous
#include <cuda_runtime.h>
#include <cstdint>

#define TOKENS 64
#define IN_F   4096
#define OUT_F  11008
#define RANK   16
#define BN     96
#define BK     32
#define NITER  (IN_F / BK)   // 128
#define NCTA   115           // ceil(11008/96)

// scratch
__device__ float g_t[TOKENS * RANK];
__device__ float g_tp[4 * TOKENS * RANK];               // k-chunk partials
__device__ float g_xfrag[NITER * 16 * 32 * 4];          // 1 MB, tf32-hi frags

// ---------------------------------------------------------------------------
__device__ __forceinline__ uint32_t smem_u32(const void* p) {
    uint32_t a;
    asm("{ .reg .u64 t; cvta.to.shared.u64 t, %1; cvt.u32.u64 %0, t; }" : "=r"(a) : "l"(p));
    return a;
}
__device__ __forceinline__ void cp16(void* dst_smem, const void* src) {
    asm volatile("cp.async.cg.shared.global [%0], [%1], 16;"
                 :: "r"(smem_u32(dst_smem)), "l"(src));
}
__device__ __forceinline__ void mma_tf32(float* d, const uint32_t* a, const uint32_t* b) {
    asm volatile("mma.sync.aligned.m16n8k8.row.col.f32.tf32.tf32.f32 "
        "{%0,%1,%2,%3}, {%4,%5,%6,%7}, {%8,%9}, {%0,%1,%2,%3};"
        : "+f"(d[0]), "+f"(d[1]), "+f"(d[2]), "+f"(d[3])
        : "r"(a[0]), "r"(a[1]), "r"(a[2]), "r"(a[3]), "r"(b[0]), "r"(b[1]));
}
__device__ __forceinline__ float tf32_rn(float v) {
    uint32_t h;
    asm("cvt.rna.tf32.f32 %0, %1;" : "=r"(h) : "f"(v));
    return __uint_as_float(h);
}

// ---------------------------------------------------------------------------
// Kernel 1: partial t: g_tp[q][m][r] = sum over k-quarter of x[m][k]*A[r][k]
// grid (64, 4) x 128 threads
// ---------------------------------------------------------------------------
__global__ void __launch_bounds__(128) lora_t_part(
    const float* __restrict__ x, const float* __restrict__ A)
{
    const int m = blockIdx.x, q = blockIdx.y, tid = threadIdx.x;
    const int wid = tid >> 5, lane = tid & 31;
    const float4* x4 = (const float4*)(x + (size_t)m * IN_F);
    const float4* A4 = (const float4*)A;

    float racc[RANK];
#pragma unroll
    for (int r = 0; r < RANK; r++) racc[r] = 0.0f;
#pragma unroll
    for (int it = 0; it < 2; it++) {
        const int k4 = q * 256 + tid + it * 128;
        const float4 xv = x4[k4];
#pragma unroll
        for (int r = 0; r < RANK; r++) {
            const float4 av = A4[r * 1024 + k4];
            racc[r] += xv.x * av.x + xv.y * av.y + xv.z * av.z + xv.w * av.w;
        }
    }
#pragma unroll
    for (int r = 0; r < RANK; r++)
#pragma unroll
        for (int o = 16; o; o >>= 1)
            racc[r] += __shfl_xor_sync(0xFFFFFFFFu, racc[r], o);

    __shared__ float sp[4][RANK];
    if (lane == 0)
#pragma unroll
        for (int r = 0; r < RANK; r++) sp[wid][r] = racc[r];
    __syncthreads();
    if (tid < RANK)
        g_tp[(q * TOKENS + m) * RANK + tid] = sp[0][tid] + sp[1][tid] + sp[2][tid] + sp[3][tid];
}

// ---------------------------------------------------------------------------
// Kernel 2: pack x into tf32-hi m16n8k8 A-fragments; block 255 also reduces t.
// ---------------------------------------------------------------------------
__global__ void __launch_bounds__(256) xfrag_kernel(const float* __restrict__ x)
{
    const int gid  = blockIdx.x * 256 + threadIdx.x;   // 65536
    const int lane = gid & 31;
    const int ks   = (gid >> 5) & 3;
    const int mt   = (gid >> 7) & 3;
    const int i    = gid >> 9;
    const int m    = mt * 16 + (lane >> 2);
    const int k    = i * BK + ks * 8 + (lane & 3);

    const float h00 = tf32_rn(x[m * IN_F + k]);
    const float h01 = tf32_rn(x[m * IN_F + k + 4]);
    const float h10 = tf32_rn(x[(m + 8) * IN_F + k]);
    const float h11 = tf32_rn(x[(m + 8) * IN_F + k + 4]);

    const int slot = mt * 4 + ks;
    *(float4*)(g_xfrag + ((size_t)i * 16 + slot) * 128 + lane * 4) =
        make_float4(h00, h10, h01, h11);

    if (blockIdx.x == 255) {   // deterministic t reduce (dep: lora_t_part launch)
        const int idx = threadIdx.x;
#pragma unroll
        for (int c = 0; c < 4; c++) {
            const int e = idx + c * 256;
            g_t[e] = g_tp[e] + g_tp[1024 + e] + g_tp[2048 + e] + g_tp[3072 + e];
        }
    }
}

// ---------------------------------------------------------------------------
// Kernel 3: single-pass tf32 GEMM, W fed raw (HW truncation, bias-corrected).
// CTA: 64 tok x 96 ch. 8 warps (2m x 4n), warp tile 32 x 24.
// ---------------------------------------------------------------------------
#define XS_SZ    8192                  // 16 slots * 128 floats
#define WS_SZ    13824                 // 96 rows * 36 floats * 4B
#define STAGE_SZ (XS_SZ + WS_SZ)       // 22016
#define SMEM_SZ  (2 * STAGE_SZ)        // 44032

__global__ void __launch_bounds__(256, 1) qgemm_tf32(
    const float* __restrict__ W,     const float* __restrict__ scale,
    const float* __restrict__ Bl,    const float* __restrict__ bias,
    float* __restrict__ out)
{
    extern __shared__ char smem[];
    const int tid  = threadIdx.x;
    const int n0   = blockIdx.x * BN;
    const int warp = tid >> 5, lane = tid & 31;
    const int wm = warp >> 2, wn = warp & 3;   // 2 x 4 warp grid
    const int g  = lane >> 2, j = lane & 3;

    float acc[2][3][4];
#pragma unroll
    for (int a = 0; a < 2; a++)
#pragma unroll
        for (int b = 0; b < 3; b++)
#pragma unroll
            for (int c = 0; c < 4; c++) acc[a][b][c] = 0.0f;

    // W loader mapping: 96 rows x 8 quads, 3 rows per thread (clamped at edge)
    const int wr = tid >> 3, wq = tid & 7;
    const float* wsrc[3];
#pragma unroll
    for (int sw = 0; sw < 3; sw++) {
        int row = n0 + wr + sw * 32;
        if (row > OUT_F - 1) row = OUT_F - 1;
        wsrc[sw] = W + (size_t)row * IN_F + wq * 4;
    }

#define ISSUE_STAGE(s) do {                                                     \
    if ((s) < NITER) {                                                          \
        char* buf = smem + ((s) & 1) * STAGE_SZ;                                \
        const float* xsrc = g_xfrag + (size_t)(s) * 2048;                       \
        _Pragma("unroll")                                                       \
        for (int c = 0; c < 2; c++)                                             \
            cp16(buf + (tid + c * 256) * 16, xsrc + (tid + c * 256) * 4);       \
        _Pragma("unroll")                                                       \
        for (int sw = 0; sw < 3; sw++)                                          \
            cp16(buf + XS_SZ + (wr + sw * 32) * 144 + wq * 16,                  \
                 wsrc[sw] + (size_t)(s) * BK);                                  \
    }                                                                           \
    asm volatile("cp.async.commit_group;" ::: "memory");                        \
} while (0)

    ISSUE_STAGE(0);
    ISSUE_STAGE(1);

#pragma unroll 1
    for (int i = 0; i < NITER; i++) {
        asm volatile("cp.async.wait_group 1;" ::: "memory");
        __syncthreads();
        const char* buf = smem + (i & 1) * STAGE_SZ;
        const uint32_t* xs = (const uint32_t*)buf;
        const uint32_t* ws = (const uint32_t*)(buf + XS_SZ);

#pragma unroll
        for (int ks = 0; ks < 4; ks++) {
            uint32_t a[2][4];
#pragma unroll
            for (int mt2 = 0; mt2 < 2; mt2++) {
                const int mt = wm * 2 + mt2;
                const uint4 v = *(const uint4*)(xs + (mt * 4 + ks) * 128 + lane * 4);
                a[mt2][0] = v.x; a[mt2][1] = v.y; a[mt2][2] = v.z; a[mt2][3] = v.w;
            }
            uint32_t b[3][2];
#pragma unroll
            for (int nt = 0; nt < 3; nt++) {
                const int n = wn * 24 + nt * 8 + g;
                b[nt][0] = ws[n * 36 + ks * 8 + j];
                b[nt][1] = ws[n * 36 + ks * 8 + j + 4];
            }
#pragma unroll
            for (int mt2 = 0; mt2 < 2; mt2++)
#pragma unroll
                for (int nt = 0; nt < 3; nt++)
                    mma_tf32(acc[mt2][nt], a[mt2], b[nt]);
        }
        __syncthreads();
        ISSUE_STAGE(i + 2);
    }

    // epilogue: tf32-truncation bias correction folded into scale
    const float corr = 1.00048828125f;   // 1 + 2^-11
#pragma unroll
    for (int mt2 = 0; mt2 < 2; mt2++) {
        const int tokA = wm * 32 + mt2 * 16 + g;
        const int tokB = tokA + 8;
        float4 tA0 = *(const float4*)(g_t + tokA * RANK);
        float4 tA1 = *(const float4*)(g_t + tokA * RANK + 4);
        float4 tA2 = *(const float4*)(g_t + tokA * RANK + 8);
        float4 tA3 = *(const float4*)(g_t + tokA * RANK + 12);
        float4 tB0 = *(const float4*)(g_t + tokB * RANK);
        float4 tB1 = *(const float4*)(g_t + tokB * RANK + 4);
        float4 tB2 = *(const float4*)(g_t + tokB * RANK + 8);
        float4 tB3 = *(const float4*)(g_t + tokB * RANK + 12);
#pragma unroll
        for (int nt = 0; nt < 3; nt++) {
            const int ch = n0 + wn * 24 + nt * 8 + 2 * j;
            if (ch >= OUT_F) continue;
            const float2 sc = *(const float2*)(scale + ch);
            const float2 bi = *(const float2*)(bias + ch);
            const float* bl0 = Bl + (size_t)ch * RANK;
            const float* bl1 = bl0 + RANK;
            float l0 = 0.f, l0b = 0.f, l1 = 0.f, l1b = 0.f;
#pragma unroll
            for (int q = 0; q < 4; q++) {
                const float4 b0 = ((const float4*)bl0)[q];
                const float4 b1 = ((const float4*)bl1)[q];
                const float4 ta = (q == 0) ? tA0 : (q == 1) ? tA1 : (q == 2) ? tA2 : tA3;
                const float4 tb = (q == 0) ? tB0 : (q == 1) ? tB1 : (q == 2) ? tB2 : tB3;
                l0  += ta.x * b0.x + ta.y * b0.y + ta.z * b0.z + ta.w * b0.w;
                l1  += ta.x * b1.x + ta.y * b1.y + ta.z * b1.z + ta.w * b1.w;
                l0b += tb.x * b0.x + tb.y * b0.y + tb.z * b0.z + tb.w * b0.w;
                l1b += tb.x * b1.x + tb.y * b1.y + tb.z * b1.z + tb.w * b1.w;
            }
            const float s0 = sc.x * corr, s1 = sc.y * corr;
            float2 oA = make_float2(acc[mt2][nt][0] * s0 + l0  + bi.x,
                                    acc[mt2][nt][1] * s1 + l1  + bi.y);
            float2 oB = make_float2(acc[mt2][nt][2] * s0 + l0b + bi.x,
                                    acc[mt2][nt][3] * s1 + l1b + bi.y);
            *(float2*)(out + (size_t)tokA * OUT_F + ch) = oA;
            *(float2*)(out + (size_t)tokB * OUT_F + ch) = oB;
        }
    }
}

// ---------------------------------------------------------------------------
extern "C" void kernel_launch(void* const* d_in, const int* in_sizes, int n_in,
                              void* d_out, int out_size)
{
    const float* x     = (const float*)d_in[0];
    const float* W     = (const float*)d_in[1];
    const float* scale = (const float*)d_in[2];
    const float* A     = (const float*)d_in[3];
    const float* B     = (const float*)d_in[4];
    const float* bias  = (const float*)d_in[5];
    float* out = (float*)d_out;

    cudaFuncSetAttribute(qgemm_tf32, cudaFuncAttributeMaxDynamicSharedMemorySize, SMEM_SZ);
    lora_t_part<<<dim3(TOKENS, 4), 128>>>(x, A);
    xfrag_kernel<<<256, 256>>>(x);
    qgemm_tf32<<<NCTA, 256, SMEM_SZ>>>(W, scale, B, bias, out);
}

// round 5
// speedup vs baseline: 5.5541x; 1.3622x over previous
#include <cuda_runtime.h>
#include <cstdint>

#define TOKENS 64
#define IN_F   4096
#define OUT_F  11008
#define RANK   16
#define BN     96
#define BK     32
#define NITER  (IN_F / BK)   // 128
#define NCTA   115           // ceil(11008/96)

// scratch
__device__ float g_tp[4 * TOKENS * RANK];               // k-quarter partials of t
__device__ float g_xfrag[NITER * 16 * 32 * 4];          // 1 MB, tf32-hi x fragments

// ---------------------------------------------------------------------------
__device__ __forceinline__ uint32_t smem_u32(const void* p) {
    uint32_t a;
    asm("{ .reg .u64 t; cvta.to.shared.u64 t, %1; cvt.u32.u64 %0, t; }" : "=r"(a) : "l"(p));
    return a;
}
__device__ __forceinline__ void cp16(void* dst_smem, const void* src) {
    asm volatile("cp.async.cg.shared.global [%0], [%1], 16;"
                 :: "r"(smem_u32(dst_smem)), "l"(src));
}
__device__ __forceinline__ void mma_tf32(float* d, const uint32_t* a, const uint32_t* b) {
    asm volatile("mma.sync.aligned.m16n8k8.row.col.f32.tf32.tf32.f32 "
        "{%0,%1,%2,%3}, {%4,%5,%6,%7}, {%8,%9}, {%0,%1,%2,%3};"
        : "+f"(d[0]), "+f"(d[1]), "+f"(d[2]), "+f"(d[3])
        : "r"(a[0]), "r"(a[1]), "r"(a[2]), "r"(a[3]), "r"(b[0]), "r"(b[1]));
}
__device__ __forceinline__ float tf32_rn(float v) {
    uint32_t h;
    asm("cvt.rna.tf32.f32 %0, %1;" : "=r"(h) : "f"(v));
    return __uint_as_float(h);
}

// ---------------------------------------------------------------------------
// Prep kernel (512 blocks x 256 threads):
//   blocks [0,256):  pack x into tf32-hi m16n8k8 A-fragments
//   blocks [256,512): t partials: block b -> (m = (b-256)>>2, q = (b-256)&3)
//                     g_tp[(q*64+m)*16+r] = sum over K-quarter q of x[m][k]A[r][k]
// ---------------------------------------------------------------------------
__global__ void __launch_bounds__(256) prep_kernel(
    const float* __restrict__ x, const float* __restrict__ A)
{
    if (blockIdx.x < 256) {
        const int gid  = blockIdx.x * 256 + threadIdx.x;   // 65536
        const int lane = gid & 31;
        const int ks   = (gid >> 5) & 3;
        const int mt   = (gid >> 7) & 3;
        const int i    = gid >> 9;
        const int m    = mt * 16 + (lane >> 2);
        const int k    = i * BK + ks * 8 + (lane & 3);

        const float h00 = tf32_rn(x[m * IN_F + k]);
        const float h01 = tf32_rn(x[m * IN_F + k + 4]);
        const float h10 = tf32_rn(x[(m + 8) * IN_F + k]);
        const float h11 = tf32_rn(x[(m + 8) * IN_F + k + 4]);

        const int slot = mt * 4 + ks;
        *(float4*)(g_xfrag + ((size_t)i * 16 + slot) * 128 + lane * 4) =
            make_float4(h00, h10, h01, h11);
    } else {
        const int b   = blockIdx.x - 256;
        const int m   = b >> 2, q = b & 3;
        const int tid = threadIdx.x;
        const int wid = tid >> 5, lane = tid & 31;
        const int k4  = q * 256 + tid;                     // one float4 per thread
        const float4 xv = ((const float4*)(x + (size_t)m * IN_F))[k4];
        const float4* A4 = (const float4*)A;

        float racc[RANK];
#pragma unroll
        for (int r = 0; r < RANK; r++) {
            const float4 av = A4[r * 1024 + k4];
            racc[r] = xv.x * av.x + xv.y * av.y + xv.z * av.z + xv.w * av.w;
        }
#pragma unroll
        for (int r = 0; r < RANK; r++)
#pragma unroll
            for (int o = 16; o; o >>= 1)
                racc[r] += __shfl_xor_sync(0xFFFFFFFFu, racc[r], o);

        __shared__ float sp[8][RANK];
        if (lane == 0)
#pragma unroll
            for (int r = 0; r < RANK; r++) sp[wid][r] = racc[r];
        __syncthreads();
        if (tid < RANK) {
            float s = 0.0f;
#pragma unroll
            for (int w = 0; w < 8; w++) s += sp[w][tid];
            g_tp[(q * TOKENS + m) * RANK + tid] = s;
        }
    }
}

// ---------------------------------------------------------------------------
// GEMM: single-pass tf32, W fed raw (HW truncation, bias-corrected via scale).
// CTA: 64 tok x 96 ch. 8 warps (2m x 4n), warp tile 32 x 24.
// 4-stage cp.async pipeline, one __syncthreads per iteration.
// ---------------------------------------------------------------------------
#define XS_SZ    8192                  // 16 slots * 128 floats
#define WS_SZ    13824                 // 96 rows * 36 floats * 4B
#define STAGE_SZ (XS_SZ + WS_SZ)       // 22016
#define NSTAGE   4
#define OFF_T    (NSTAGE * STAGE_SZ)   // 88064
#define SMEM_SZ  (OFF_T + TOKENS * RANK * 4)   // 92160

__global__ void __launch_bounds__(256, 1) qgemm_tf32(
    const float* __restrict__ W,     const float* __restrict__ scale,
    const float* __restrict__ Bl,    const float* __restrict__ bias,
    float* __restrict__ out)
{
    extern __shared__ char smem[];
    float* sT = (float*)(smem + OFF_T);
    const int tid  = threadIdx.x;
    const int n0   = blockIdx.x * BN;
    const int warp = tid >> 5, lane = tid & 31;
    const int wm = warp >> 2, wn = warp & 3;   // 2 x 4 warp grid
    const int g  = lane >> 2, j = lane & 3;

    float acc[2][3][4];
#pragma unroll
    for (int a = 0; a < 2; a++)
#pragma unroll
        for (int b = 0; b < 3; b++)
#pragma unroll
            for (int c = 0; c < 4; c++) acc[a][b][c] = 0.0f;

    // W loader mapping: 96 rows x 8 quads, 3 rows per thread (clamped at edge)
    const int wr = tid >> 3, wq = tid & 7;
    const float* wsrc[3];
#pragma unroll
    for (int sw = 0; sw < 3; sw++) {
        int row = n0 + wr + sw * 32;
        if (row > OUT_F - 1) row = OUT_F - 1;
        wsrc[sw] = W + (size_t)row * IN_F + wq * 4;
    }

#define ISSUE_STAGE(s) do {                                                     \
    if ((s) < NITER) {                                                          \
        char* buf = smem + ((s) & 3) * STAGE_SZ;                                \
        const float* xsrc = g_xfrag + (size_t)(s) * 2048;                       \
        _Pragma("unroll")                                                       \
        for (int c = 0; c < 2; c++)                                             \
            cp16(buf + (tid + c * 256) * 16, xsrc + (tid + c * 256) * 4);       \
        _Pragma("unroll")                                                       \
        for (int sw = 0; sw < 3; sw++)                                          \
            cp16(buf + XS_SZ + (wr + sw * 32) * 144 + wq * 16,                  \
                 wsrc[sw] + (size_t)(s) * BK);                                  \
    }                                                                           \
    asm volatile("cp.async.commit_group;" ::: "memory");                        \
} while (0)

    ISSUE_STAGE(0);
    ISSUE_STAGE(1);
    ISSUE_STAGE(2);

    // reduce t partials into smem (overlaps with in-flight stages)
#pragma unroll
    for (int c = 0; c < 4; c++) {
        const int e = tid + c * 256;
        sT[e] = g_tp[e] + g_tp[1024 + e] + g_tp[2048 + e] + g_tp[3072 + e];
    }

#pragma unroll 1
    for (int i = 0; i < NITER; i++) {
        asm volatile("cp.async.wait_group 2;" ::: "memory");
        __syncthreads();
        const char* buf = smem + (i & 3) * STAGE_SZ;
        const uint32_t* xs = (const uint32_t*)buf;
        const uint32_t* ws = (const uint32_t*)(buf + XS_SZ);

#pragma unroll
        for (int ks = 0; ks < 4; ks++) {
            uint32_t a[2][4];
#pragma unroll
            for (int mt2 = 0; mt2 < 2; mt2++) {
                const int mt = wm * 2 + mt2;
                const uint4 v = *(const uint4*)(xs + (mt * 4 + ks) * 128 + lane * 4);
                a[mt2][0] = v.x; a[mt2][1] = v.y; a[mt2][2] = v.z; a[mt2][3] = v.w;
            }
            uint32_t b[3][2];
#pragma unroll
            for (int nt = 0; nt < 3; nt++) {
                const int n = wn * 24 + nt * 8 + g;
                b[nt][0] = ws[n * 36 + ks * 8 + j];
                b[nt][1] = ws[n * 36 + ks * 8 + j + 4];
            }
#pragma unroll
            for (int mt2 = 0; mt2 < 2; mt2++)
#pragma unroll
                for (int nt = 0; nt < 3; nt++)
                    mma_tf32(acc[mt2][nt], a[mt2], b[nt]);
        }
        // safe without a second barrier: stage i+3 writes buffer (i+3)&3,
        // which nobody reads until iter i+3; stages i+1, i+2 are in flight.
        ISSUE_STAGE(i + 3);
    }

    // epilogue: tf32-truncation bias correction folded into scale
    const float corr = 1.00048828125f;   // 1 + 2^-11
#pragma unroll
    for (int mt2 = 0; mt2 < 2; mt2++) {
        const int tokA = wm * 32 + mt2 * 16 + g;
        const int tokB = tokA + 8;
        float4 tA0 = *(const float4*)(sT + tokA * RANK);
        float4 tA1 = *(const float4*)(sT + tokA * RANK + 4);
        float4 tA2 = *(const float4*)(sT + tokA * RANK + 8);
        float4 tA3 = *(const float4*)(sT + tokA * RANK + 12);
        float4 tB0 = *(const float4*)(sT + tokB * RANK);
        float4 tB1 = *(const float4*)(sT + tokB * RANK + 4);
        float4 tB2 = *(const float4*)(sT + tokB * RANK + 8);
        float4 tB3 = *(const float4*)(sT + tokB * RANK + 12);
#pragma unroll
        for (int nt = 0; nt < 3; nt++) {
            const int ch = n0 + wn * 24 + nt * 8 + 2 * j;
            if (ch >= OUT_F) continue;
            const float2 sc = *(const float2*)(scale + ch);
            const float2 bi = *(const float2*)(bias + ch);
            const float* bl0 = Bl + (size_t)ch * RANK;
            const float* bl1 = bl0 + RANK;
            float l0 = 0.f, l0b = 0.f, l1 = 0.f, l1b = 0.f;
#pragma unroll
            for (int q = 0; q < 4; q++) {
                const float4 b0 = ((const float4*)bl0)[q];
                const float4 b1 = ((const float4*)bl1)[q];
                const float4 ta = (q == 0) ? tA0 : (q == 1) ? tA1 : (q == 2) ? tA2 : tA3;
                const float4 tb = (q == 0) ? tB0 : (q == 1) ? tB1 : (q == 2) ? tB2 : tB3;
                l0  += ta.x * b0.x + ta.y * b0.y + ta.z * b0.z + ta.w * b0.w;
                l1  += ta.x * b1.x + ta.y * b1.y + ta.z * b1.z + ta.w * b1.w;
                l0b += tb.x * b0.x + tb.y * b0.y + tb.z * b0.z + tb.w * b0.w;
                l1b += tb.x * b1.x + tb.y * b1.y + tb.z * b1.z + tb.w * b1.w;
            }
            const float s0 = sc.x * corr, s1 = sc.y * corr;
            float2 oA = make_float2(acc[mt2][nt][0] * s0 + l0  + bi.x,
                                    acc[mt2][nt][1] * s1 + l1  + bi.y);
            float2 oB = make_float2(acc[mt2][nt][2] * s0 + l0b + bi.x,
                                    acc[mt2][nt][3] * s1 + l1b + bi.y);
            *(float2*)(out + (size_t)tokA * OUT_F + ch) = oA;
            *(float2*)(out + (size_t)tokB * OUT_F + ch) = oB;
        }
    }
}

// ---------------------------------------------------------------------------
extern "C" void kernel_launch(void* const* d_in, const int* in_sizes, int n_in,
                              void* d_out, int out_size)
{
    const float* x     = (const float*)d_in[0];
    const float* W     = (const float*)d_in[1];
    const float* scale = (const float*)d_in[2];
    const float* A     = (const float*)d_in[3];
    const float* B     = (const float*)d_in[4];
    const float* bias  = (const float*)d_in[5];
    float* out = (float*)d_out;

    cudaFuncSetAttribute(qgemm_tf32, cudaFuncAttributeMaxDynamicSharedMemorySize, SMEM_SZ);
    prep_kernel<<<512, 256>>>(x, A);
    qgemm_tf32<<<NCTA, 256, SMEM_SZ>>>(W, scale, B, bias, out);
}